// round 10
// baseline (speedup 1.0000x reference)
#include <cuda_runtime.h>
#include <cuda_bf16.h>
#include <cuda_fp16.h>
#include <cstdint>
#include <cstddef>

// ---------------- problem constants ----------------
#define NB    32768
#define INDIM 128
#define LATD  64
#define KCB   8192
#define NTILE 64
#define NTILES (KCB / NTILE)        // 128
#define TILE_U32 4096               // VQ per-tile fragment plane
#define TILE_BYTES 16384

// VQ scales (proven): A x 2^8, B x 2^17 -> 2*dot = C * 2^-24
#define ASCALE 256.0f
#define BSCALE 131072.0f
#define DESCALE 5.9604644775390625e-8f  // 2^-24

// decoder MLP scales: act x 2^4, W x 2^12 -> dot = C * 2^-16
#define MLP_AS 16.0f
#define MLP_WS 4096.0f
#define MLP_DS 1.52587890625e-5f        // 2^-16

#define RT_TOT (NB / 16)                 // 2048 row-tiles

// one-hot zero-fill split (float4 units of 1048576)
#define OH_TOT_F4 ((size_t)NB * KCB / 4)      // 67108864
#define Z_PREP ((size_t)16 * 1048576)
#define Z_L1   ((size_t)26 * 1048576)
#define Z_L2   ((size_t)20 * 1048576)
#define Z_L3   (OH_TOT_F4 - Z_PREP - Z_L1 - Z_L2)

// ---------------- scratch (device globals; no allocations) ----------------
__device__ float g_lat[(size_t)NB * LATD];
__device__ float g_q[(size_t)NB * LATD];
__device__ float g_embn[KCB];
__device__ uint32_t g_embF[(size_t)NTILES * TILE_U32];
__device__ float g_partial[256];

// activation fragment planes
__device__ uint4 g_xF [(size_t)RT_TOT * 8 * 3 * 32];
__device__ uint4 g_h1F[(size_t)RT_TOT * 16 * 3 * 32];
__device__ uint4 g_h2F[(size_t)RT_TOT * 8 * 3 * 32];
__device__ uint4 g_qF [(size_t)RT_TOT * 4 * 2 * 32];
__device__ uint4 g_h3F[(size_t)RT_TOT * 8 * 2 * 32];
__device__ uint4 g_h4F[(size_t)RT_TOT * 16 * 2 * 32];

// weight fragment planes, layer offsets (uint4 units)
#define OFF_W1 0
#define OFF_W2 12288
#define OFF_W3 24576
#define OFF_W4 27648
#define OFF_W5 29696
#define OFF_W6 37888
#define OFF_W7 46080
__device__ uint4 g_wF[54272];

// ---------------- helpers ----------------
__device__ __forceinline__ uint32_t smem_u32(const void* p) {
    uint32_t a;
    asm("{ .reg .u64 t; cvta.to.shared.u64 t, %1; cvt.u32.u64 %0, t; }" : "=r"(a) : "l"(p));
    return a;
}
__device__ __forceinline__ void cp16(uint32_t dst, const void* src) {
    asm volatile("cp.async.cg.shared.global [%0], [%1], 16;" :: "r"(dst), "l"(src));
}
__device__ __forceinline__ void split2h(float v, unsigned short& s0, unsigned short& s1) {
    __half h0 = __float2half_rn(v);
    float r = v - __half2float(h0);
    __half h1 = __float2half_rn(r);
    s0 = __half_as_ushort(h0);
    s1 = __half_as_ushort(h1);
}
__device__ __forceinline__ void split3b(float v, unsigned short& s0, unsigned short& s1, unsigned short& s2) {
    __nv_bfloat16 b0 = __float2bfloat16_rn(v);
    float r1 = v - __bfloat162float(b0);
    __nv_bfloat16 b1 = __float2bfloat16_rn(r1);
    float r2 = r1 - __bfloat162float(b1);
    __nv_bfloat16 b2 = __float2bfloat16_rn(r2);
    s0 = __bfloat16_as_ushort(b0);
    s1 = __bfloat16_as_ushort(b1);
    s2 = __bfloat16_as_ushort(b2);
}
__device__ __forceinline__ void mma_f16(float* C, const uint32_t* A, uint32_t b0, uint32_t b1) {
    asm volatile("mma.sync.aligned.m16n8k16.row.col.f32.f16.f16.f32 "
        "{%0,%1,%2,%3}, {%4,%5,%6,%7}, {%8,%9}, {%0,%1,%2,%3};"
        : "+f"(C[0]), "+f"(C[1]), "+f"(C[2]), "+f"(C[3])
        : "r"(A[0]), "r"(A[1]), "r"(A[2]), "r"(A[3]), "r"(b0), "r"(b1));
}
__device__ __forceinline__ void mma_bf16(float* C, const uint32_t* A, uint32_t b0, uint32_t b1) {
    asm volatile("mma.sync.aligned.m16n8k16.row.col.f32.bf16.bf16.f32 "
        "{%0,%1,%2,%3}, {%4,%5,%6,%7}, {%8,%9}, {%0,%1,%2,%3};"
        : "+f"(C[0]), "+f"(C[1]), "+f"(C[2]), "+f"(C[3])
        : "r"(A[0]), "r"(A[1]), "r"(A[2]), "r"(A[3]), "r"(b0), "r"(b1));
}
__device__ __forceinline__ uint32_t pack2(unsigned short a, unsigned short b) {
    return (uint32_t)a | ((uint32_t)b << 16);
}
// grid-stride coalesced zero fill of a float4 range
__device__ __forceinline__ void zfill(float4* __restrict__ buf, size_t z0, size_t zn,
                                      size_t gtid, size_t nthreads) {
    const float4 z = make_float4(0.f, 0.f, 0.f, 0.f);
    for (size_t i = gtid; i < zn; i += nthreads)
        buf[z0 + i] = z;
}

// ---------------- prep bodies (device functions, fused into one launch) ----------------
__device__ __forceinline__ void embn_body(const float* __restrict__ emb, int t) {
    int code = t >> 5;
    int lane = t & 31;
    if (code >= KCB) return;
    float v0 = emb[code * 64 + lane];
    float v1 = emb[code * 64 + 32 + lane];
    float s = fmaf(v0, v0, v1 * v1);
    #pragma unroll
    for (int off = 16; off; off >>= 1)
        s += __shfl_down_sync(0xffffffffu, s, off);
    if (lane == 0) g_embn[code] = s;
}

__device__ __forceinline__ void embfrag_body(const float* __restrict__ emb, int idx) {
    if (idx >= NTILES * 4 * 2 * 8 * 32) return;
    int l = idx & 31;
    int r = idx >> 5;
    int n = r & 7;
    int r2 = r >> 3;
    int s = r2 & 1;
    int r3 = r2 >> 1;
    int kt = r3 & 3;
    int t = r3 >> 2;
    int g = l >> 2, tg = l & 3;
    int code = t * 64 + n * 8 + g;
    const float* e = emb + (size_t)code * 64 + kt * 16;
    float vv[4] = {e[2 * tg] * BSCALE, e[2 * tg + 1] * BSCALE,
                   e[2 * tg + 8] * BSCALE, e[2 * tg + 9] * BSCALE};
    unsigned short p[4];
    #pragma unroll
    for (int i = 0; i < 4; i++) {
        unsigned short c0, c1;
        split2h(vv[i], c0, c1);
        p[i] = (s == 0) ? c0 : c1;
    }
    uint2 out;
    out.x = pack2(p[0], p[1]);
    out.y = pack2(p[2], p[3]);
    ((uint2*)g_embF)[idx] = out;
}

__device__ __forceinline__ void wfrag_bf3_body(const float* __restrict__ W, uint4* __restrict__ out,
                                               int KT, int NOUTL, int idx) {
    if (idx >= KT * 3 * (NOUTL / 16) * 32) return;
    int l = idx & 31;
    int t2 = idx >> 5;
    int np = t2 % (NOUTL / 16);
    int t3 = t2 / (NOUTL / 16);
    int s = t3 % 3;
    int kt = t3 / 3;
    int g = l >> 2, tg = l & 3;
    int Kw = KT * 16;
    uint32_t r[4];
    #pragma unroll
    for (int j = 0; j < 2; j++) {
        int n = 2 * np + j;
        const float* e = W + (size_t)(n * 8 + g) * Kw + kt * 16;
        float vv[4] = {e[2 * tg], e[2 * tg + 1], e[2 * tg + 8], e[2 * tg + 9]};
        unsigned short sel[4];
        #pragma unroll
        for (int i = 0; i < 4; i++) {
            unsigned short a, b, c;
            split3b(vv[i], a, b, c);
            sel[i] = (s == 0) ? a : (s == 1) ? b : c;
        }
        r[2 * j + 0] = pack2(sel[0], sel[1]);
        r[2 * j + 1] = pack2(sel[2], sel[3]);
    }
    out[idx] = make_uint4(r[0], r[1], r[2], r[3]);
}

__device__ __forceinline__ void wfrag_fp2_body(const float* __restrict__ W, uint4* __restrict__ out,
                                               int KT, int NOUTL, int idx) {
    if (idx >= KT * 2 * (NOUTL / 16) * 32) return;
    int l = idx & 31;
    int t2 = idx >> 5;
    int np = t2 % (NOUTL / 16);
    int t3 = t2 / (NOUTL / 16);
    int s = t3 & 1;
    int kt = t3 >> 1;
    int g = l >> 2, tg = l & 3;
    int Kw = KT * 16;
    uint32_t r[4];
    #pragma unroll
    for (int j = 0; j < 2; j++) {
        int n = 2 * np + j;
        const float* e = W + (size_t)(n * 8 + g) * Kw + kt * 16;
        float vv[4] = {e[2 * tg] * MLP_WS, e[2 * tg + 1] * MLP_WS,
                       e[2 * tg + 8] * MLP_WS, e[2 * tg + 9] * MLP_WS};
        unsigned short sel[4];
        #pragma unroll
        for (int i = 0; i < 4; i++) {
            unsigned short a, b;
            split2h(vv[i], a, b);
            sel[i] = (s == 0) ? a : b;
        }
        r[2 * j + 0] = pack2(sel[0], sel[1]);
        r[2 * j + 1] = pack2(sel[2], sel[3]);
    }
    out[idx] = make_uint4(r[0], r[1], r[2], r[3]);
}

__device__ __forceinline__ void convA_bf3_body(const float* __restrict__ in, uint4* __restrict__ out,
                                               int KT, int idx) {
    if (idx >= RT_TOT * KT * 32) return;
    int l = idx & 31;
    int t2 = idx >> 5;
    int kt = t2 % KT;
    int rt = t2 / KT;
    int g = l >> 2, tg = l & 3;
    int Kw = KT * 16;
    const float* p = in + (size_t)(rt * 16 + g) * Kw + kt * 16 + 2 * tg;
    float2 v0 = *(const float2*)p;
    float2 v1 = *(const float2*)(p + 8);
    float2 v2 = *(const float2*)(p + 8 * Kw);
    float2 v3 = *(const float2*)(p + 8 * Kw + 8);
    float vv[8] = {v0.x, v0.y, v2.x, v2.y, v1.x, v1.y, v3.x, v3.y};
    unsigned short us[8][3];
    #pragma unroll
    for (int i = 0; i < 8; i++) split3b(vv[i], us[i][0], us[i][1], us[i][2]);
    size_t base = (size_t)t2 * 3 * 32 + l;
    #pragma unroll
    for (int s = 0; s < 3; s++)
        out[base + (size_t)s * 32] = make_uint4(pack2(us[0][s], us[1][s]), pack2(us[2][s], us[3][s]),
                                                pack2(us[4][s], us[5][s]), pack2(us[6][s], us[7][s]));
}

// fused prep + one-hot zero-fill slice
__global__ __launch_bounds__(256) void prep_kernel(
    const float* __restrict__ emb, const float* __restrict__ x,
    const float* __restrict__ eW1, const float* __restrict__ eW2, const float* __restrict__ eW3,
    const float* __restrict__ dW1, const float* __restrict__ dW2,
    const float* __restrict__ dWmu, const float* __restrict__ dWlv,
    float* __restrict__ onehot)
{
    int bid = blockIdx.x;
    int tid = threadIdx.x;
    if (bid < 1024) {
        embn_body(emb, bid * 256 + tid);
    } else if (bid < 2048) {
        embfrag_body(emb, (bid - 1024) * 256 + tid);
    } else if (bid < 2096) {
        wfrag_bf3_body(eW1, g_wF + OFF_W1, 8, 256, (bid - 2048) * 256 + tid);
    } else if (bid < 2144) {
        wfrag_bf3_body(eW2, g_wF + OFF_W2, 16, 128, (bid - 2096) * 256 + tid);
    } else if (bid < 2156) {
        wfrag_bf3_body(eW3, g_wF + OFF_W3, 8, 64, (bid - 2144) * 256 + tid);
    } else if (bid < 2164) {
        wfrag_fp2_body(dW1, g_wF + OFF_W4, 4, 128, (bid - 2156) * 256 + tid);
    } else if (bid < 2196) {
        wfrag_fp2_body(dW2, g_wF + OFF_W5, 8, 256, (bid - 2164) * 256 + tid);
    } else if (bid < 2228) {
        wfrag_fp2_body(dWmu, g_wF + OFF_W6, 16, 128, (bid - 2196) * 256 + tid);
    } else if (bid < 2260) {
        wfrag_fp2_body(dWlv, g_wF + OFF_W7, 16, 128, (bid - 2228) * 256 + tid);
    } else {
        convA_bf3_body(x, g_xF, 8, (bid - 2260) * 256 + tid);
    }
    // zero-fill slice [0, Z_PREP)
    zfill((float4*)onehot, 0, Z_PREP,
          (size_t)bid * 256 + tid, (size_t)gridDim.x * 256);
}

__global__ void convA_fp2(const float* __restrict__ in, uint4* __restrict__ out, int KT) {
    int idx = blockIdx.x * 256 + threadIdx.x;
    if (idx >= RT_TOT * KT * 32) return;
    int l = idx & 31;
    int t2 = idx >> 5;
    int kt = t2 % KT;
    int rt = t2 / KT;
    int g = l >> 2, tg = l & 3;
    int Kw = KT * 16;
    const float* p = in + (size_t)(rt * 16 + g) * Kw + kt * 16 + 2 * tg;
    float2 v0 = *(const float2*)p;
    float2 v1 = *(const float2*)(p + 8);
    float2 v2 = *(const float2*)(p + 8 * Kw);
    float2 v3 = *(const float2*)(p + 8 * Kw + 8);
    float vv[8] = {v0.x, v0.y, v2.x, v2.y, v1.x, v1.y, v3.x, v3.y};
    unsigned short us[8][2];
    #pragma unroll
    for (int i = 0; i < 8; i++) split2h(vv[i] * MLP_AS, us[i][0], us[i][1]);
    size_t base = (size_t)t2 * 2 * 32 + l;
    #pragma unroll
    for (int s = 0; s < 2; s++)
        out[base + (size_t)s * 32] = make_uint4(pack2(us[0][s], us[1][s]), pack2(us[2][s], us[3][s]),
                                                pack2(us[4][s], us[5][s]), pack2(us[6][s], us[7][s]));
}

// ---------------- tensor MLP layer (round-9 interleave + optional zero-fill tail) ----------------
// OUTMODE: 0 = bf3 frag planes, 1 = fp2 frag planes (x MLP_AS), 2 = fp32 row-major
template <int KT, int NOUT, int CTILE, bool RELU, bool INBF, int OUTMODE>
__global__ __launch_bounds__(256, 2) void hmlp_kernel(
    const uint4* __restrict__ Af, const uint4* __restrict__ Wf,
    const float* __restrict__ bias, float dscale,
    float* __restrict__ outF, uint4* __restrict__ outFrag,
    const uint4* __restrict__ Wf2, const float* __restrict__ bias2,
    float* __restrict__ outF2,
    float* __restrict__ zbuf, size_t z0, size_t zn)
{
    constexpr int INS = INBF ? 3 : 2;
    constexpr int NCOL = CTILE / 8;
    constexpr int NPT = CTILE / 16;      // column pairs in this CTA tile
    constexpr int NPW = NOUT / 16;       // total column pairs
    constexpr int GP = INBF ? 2 : 4;     // npp group size for interleave
    constexpr int NG = NPT / GP;
    const int l = threadIdx.x & 31;
    const int wid = threadIdx.x >> 5;
    const int rt = blockIdx.x * 8 + wid;
    const int c0 = blockIdx.y * CTILE;
    const int np0 = c0 >> 4;

    if (blockIdx.z) { Wf = Wf2; bias = bias2; outF = outF2; }

    float C[NCOL][4];
    #pragma unroll
    for (int n = 0; n < NCOL; n++)
        C[n][0] = C[n][1] = C[n][2] = C[n][3] = 0.0f;

    for (int kt = 0; kt < KT; kt++) {
        const uint4* ab = Af + (size_t)(rt * KT + kt) * INS * 32 + l;
        uint4 a0 = ab[0];
        uint4 a1 = ab[32];
        uint4 a2;
        if constexpr (INBF) a2 = ab[64];
        const uint4* wb = Wf + ((size_t)kt * INS * NPW + np0) * 32 + l;
        #pragma unroll
        for (int grp = 0; grp < NG; grp++) {
            uint4 u[GP][INS];
            #pragma unroll
            for (int j = 0; j < GP; j++)
                #pragma unroll
                for (int s = 0; s < INS; s++)
                    u[j][s] = wb[(s * NPW + grp * GP + j) * 32];
            #pragma unroll
            for (int j = 0; j < GP; j++) {
                int n0 = 2 * (grp * GP + j);
                if constexpr (INBF) {
                    mma_bf16(C[n0],     (const uint32_t*)&a0, u[j][0].x, u[j][0].y);
                    mma_bf16(C[n0 + 1], (const uint32_t*)&a0, u[j][0].z, u[j][0].w);
                } else {
                    mma_f16(C[n0],     (const uint32_t*)&a0, u[j][0].x, u[j][0].y);
                    mma_f16(C[n0 + 1], (const uint32_t*)&a0, u[j][0].z, u[j][0].w);
                }
            }
            #pragma unroll
            for (int j = 0; j < GP; j++) {
                int n0 = 2 * (grp * GP + j);
                if constexpr (INBF) {
                    mma_bf16(C[n0],     (const uint32_t*)&a0, u[j][1].x, u[j][1].y);
                    mma_bf16(C[n0 + 1], (const uint32_t*)&a0, u[j][1].z, u[j][1].w);
                } else {
                    mma_f16(C[n0],     (const uint32_t*)&a0, u[j][1].x, u[j][1].y);
                    mma_f16(C[n0 + 1], (const uint32_t*)&a0, u[j][1].z, u[j][1].w);
                }
            }
            #pragma unroll
            for (int j = 0; j < GP; j++) {
                int n0 = 2 * (grp * GP + j);
                if constexpr (INBF) {
                    mma_bf16(C[n0],     (const uint32_t*)&a1, u[j][0].x, u[j][0].y);
                    mma_bf16(C[n0 + 1], (const uint32_t*)&a1, u[j][0].z, u[j][0].w);
                } else {
                    mma_f16(C[n0],     (const uint32_t*)&a1, u[j][0].x, u[j][0].y);
                    mma_f16(C[n0 + 1], (const uint32_t*)&a1, u[j][0].z, u[j][0].w);
                }
            }
            if constexpr (INBF) {
                #pragma unroll
                for (int j = 0; j < GP; j++) {
                    int n0 = 2 * (grp * GP + j);
                    mma_bf16(C[n0],     (const uint32_t*)&a1, u[j][1].x, u[j][1].y);
                    mma_bf16(C[n0 + 1], (const uint32_t*)&a1, u[j][1].z, u[j][1].w);
                }
                #pragma unroll
                for (int j = 0; j < GP; j++) {
                    int n0 = 2 * (grp * GP + j);
                    mma_bf16(C[n0],     (const uint32_t*)&a0, u[j][2].x, u[j][2].y);
                    mma_bf16(C[n0 + 1], (const uint32_t*)&a0, u[j][2].z, u[j][2].w);
                }
                #pragma unroll
                for (int j = 0; j < GP; j++) {
                    int n0 = 2 * (grp * GP + j);
                    mma_bf16(C[n0],     (const uint32_t*)&a2, u[j][0].x, u[j][0].y);
                    mma_bf16(C[n0 + 1], (const uint32_t*)&a2, u[j][0].z, u[j][0].w);
                }
            }
        }
    }

    const int g = l >> 2, tg = l & 3;
    #pragma unroll
    for (int n = 0; n < NCOL; n++) {
        float2 b = *(const float2*)&bias[c0 + n * 8 + 2 * tg];
        C[n][0] = __fadd_rn(__fmul_rn(C[n][0], dscale), b.x);
        C[n][1] = __fadd_rn(__fmul_rn(C[n][1], dscale), b.y);
        C[n][2] = __fadd_rn(__fmul_rn(C[n][2], dscale), b.x);
        C[n][3] = __fadd_rn(__fmul_rn(C[n][3], dscale), b.y);
        if (RELU) {
            C[n][0] = fmaxf(C[n][0], 0.0f);
            C[n][1] = fmaxf(C[n][1], 0.0f);
            C[n][2] = fmaxf(C[n][2], 0.0f);
            C[n][3] = fmaxf(C[n][3], 0.0f);
        }
    }

    if constexpr (OUTMODE == 2) {
        const int row0 = rt * 16 + g;
        #pragma unroll
        for (int n = 0; n < NCOL; n++) {
            float* po = outF + (size_t)row0 * NOUT + c0 + n * 8 + 2 * tg;
            *(float2*)po = make_float2(C[n][0], C[n][1]);
            *(float2*)(po + (size_t)8 * NOUT) = make_float2(C[n][2], C[n][3]);
        }
    } else if constexpr (OUTMODE == 0) {
        #pragma unroll
        for (int ktl = 0; ktl < NCOL / 2; ktl++) {
            float vv[8] = {C[2 * ktl][0], C[2 * ktl][1], C[2 * ktl][2], C[2 * ktl][3],
                           C[2 * ktl + 1][0], C[2 * ktl + 1][1], C[2 * ktl + 1][2], C[2 * ktl + 1][3]};
            unsigned short us[8][3];
            #pragma unroll
            for (int i = 0; i < 8; i++) split3b(vv[i], us[i][0], us[i][1], us[i][2]);
            size_t base = (size_t)(rt * (NOUT / 16) + np0 + ktl) * 3 * 32 + l;
            #pragma unroll
            for (int s = 0; s < 3; s++)
                outFrag[base + (size_t)s * 32] =
                    make_uint4(pack2(us[0][s], us[1][s]), pack2(us[2][s], us[3][s]),
                               pack2(us[4][s], us[5][s]), pack2(us[6][s], us[7][s]));
        }
    } else {
        #pragma unroll
        for (int ktl = 0; ktl < NCOL / 2; ktl++) {
            float vv[8] = {C[2 * ktl][0], C[2 * ktl][1], C[2 * ktl][2], C[2 * ktl][3],
                           C[2 * ktl + 1][0], C[2 * ktl + 1][1], C[2 * ktl + 1][2], C[2 * ktl + 1][3]};
            unsigned short us[8][2];
            #pragma unroll
            for (int i = 0; i < 8; i++) split2h(vv[i] * MLP_AS, us[i][0], us[i][1]);
            size_t base = (size_t)(rt * (NOUT / 16) + np0 + ktl) * 2 * 32 + l;
            #pragma unroll
            for (int s = 0; s < 2; s++)
                outFrag[base + (size_t)s * 32] =
                    make_uint4(pack2(us[0][s], us[1][s]), pack2(us[2][s], us[3][s]),
                               pack2(us[4][s], us[5][s]), pack2(us[6][s], us[7][s]));
        }
    }

    // one-hot zero-fill tail (stores overlap with other CTAs' compute)
    if (zbuf) {
        size_t nblk = (size_t)gridDim.x * gridDim.y * gridDim.z;
        size_t bidl = blockIdx.x + (size_t)gridDim.x * (blockIdx.y + (size_t)gridDim.y * blockIdx.z);
        zfill((float4*)zbuf, z0, zn, bidl * 256 + threadIdx.x, nblk * 256);
    }
}

// ---------------- VQ kernel (zero-fill removed; numerics identical) ----------------
#define SM_EMBN 32768
#define SM_LATN 65536
#define SM_MINI 66048
#define VQ_SMEM 66560

__global__ __launch_bounds__(256, 2) void vq_mma_kernel(const float* __restrict__ lat,
                                                        const float* __restrict__ emb,
                                                        float* __restrict__ onehot,
                                                        float* __restrict__ qout) {
    extern __shared__ __align__(16) unsigned char smem[];
    float* EMBN = (float*)(smem + SM_EMBN);
    float* LATN = (float*)(smem + SM_LATN);
    int*   SMINI = (int*)(smem + SM_MINI);
    const int tid = threadIdx.x;
    const int w = tid >> 5, l = tid & 31, g = l >> 2, tg = l & 3;
    const int r0 = blockIdx.x * 128;
    const uint32_t sb = smem_u32(smem);

    {
        const char* src = (const char*)g_embF;
        #pragma unroll
        for (int i = 0; i < 4; i++)
            cp16(sb + (uint32_t)(i * 256 + tid) * 16u, src + (size_t)(i * 256 + tid) * 16);
        asm volatile("cp.async.commit_group;" ::: "memory");
    }
    {
        float4* d = (float4*)EMBN;
        const float4* s = (const float4*)(lat + (size_t)r0 * 64);
        #pragma unroll
        for (int i = 0; i < 8; i++) d[i * 256 + tid] = s[i * 256 + tid];
    }
    __syncthreads();

    if (tid < 128) {
        const float* row = EMBN + tid * 64;
        float s = 0.0f;
        for (int j = 0; j < 64; j++) s = fmaf(row[j], row[j], s);
        LATN[tid] = s;
    }

    uint32_t A0[4][4], A1[4][4];
    {
        const float2* L2 = (const float2*)EMBN;
        int row0 = w * 16 + g;
        #pragma unroll
        for (int kt = 0; kt < 4; kt++) {
            #pragma unroll
            for (int half = 0; half < 2; half++) {
                int rr = row0 + half * 8;
                #pragma unroll
                for (int chunk = 0; chunk < 2; chunk++) {
                    float2 v = L2[rr * 32 + kt * 8 + tg + chunk * 4];
                    unsigned short x0, x1, y0, y1;
                    split2h(v.x * ASCALE, x0, x1);
                    split2h(v.y * ASCALE, y0, y1);
                    int ai = half + 2 * chunk;
                    A0[kt][ai] = pack2(x0, y0);
                    A1[kt][ai] = pack2(x1, y1);
                }
            }
        }
    }
    __syncthreads();
    {
        float4* d = (float4*)EMBN;
        const float4* s = (const float4*)g_embn;
        #pragma unroll
        for (int i = 0; i < 8; i++) d[i * 256 + tid] = s[i * 256 + tid];
    }
    __syncthreads();
    const float ln0 = LATN[w * 16 + g];
    const float ln1 = LATN[w * 16 + g + 8];

    float minv0 = 3.402823466e38f, minv1 = 3.402823466e38f;
    int mini0 = 0, mini1 = 0;

    for (int t = 0; t < NTILES; t++) {
        const int cur = t & 1;
        if (t + 1 < NTILES) {
            const uint32_t dst = sb + (uint32_t)(cur ^ 1) * TILE_BYTES;
            const char* src = (const char*)g_embF + (size_t)(t + 1) * TILE_BYTES;
            #pragma unroll
            for (int i = 0; i < 4; i++)
                cp16(dst + (uint32_t)(i * 256 + tid) * 16u, src + (size_t)(i * 256 + tid) * 16);
            asm volatile("cp.async.commit_group;" ::: "memory");
            asm volatile("cp.async.wait_group 1;" ::: "memory");
        } else {
            asm volatile("cp.async.wait_group 0;" ::: "memory");
        }
        __syncthreads();

        const uint2* BT = (const uint2*)(smem + (size_t)cur * TILE_BYTES);
        #pragma unroll
        for (int batch = 0; batch < 2; batch++) {
            float C[4][4];
            #pragma unroll
            for (int c = 0; c < 4; c++)
                C[c][0] = C[c][1] = C[c][2] = C[c][3] = 0.0f;
            #pragma unroll
            for (int kt = 0; kt < 4; kt++) {
                #pragma unroll
                for (int c = 0; c < 4; c++) {
                    const int n = batch * 4 + c;
                    uint2 b0 = BT[((kt * 2 + 0) * 8 + n) * 32 + l];
                    uint2 b1 = BT[((kt * 2 + 1) * 8 + n) * 32 + l];
                    mma_f16(C[c], A0[kt], b0.x, b0.y);
                    mma_f16(C[c], A0[kt], b1.x, b1.y);
                    mma_f16(C[c], A1[kt], b0.x, b0.y);
                }
            }
            #pragma unroll
            for (int c = 0; c < 4; c++) {
                const int code0 = t * 64 + (batch * 4 + c) * 8 + 2 * tg;
                float2 en = *(const float2*)(EMBN + code0);
                float d00 = __fsub_rn(__fadd_rn(ln0, en.x), __fmul_rn(C[c][0], DESCALE));
                float d01 = __fsub_rn(__fadd_rn(ln0, en.y), __fmul_rn(C[c][1], DESCALE));
                float d10 = __fsub_rn(__fadd_rn(ln1, en.x), __fmul_rn(C[c][2], DESCALE));
                float d11 = __fsub_rn(__fadd_rn(ln1, en.y), __fmul_rn(C[c][3], DESCALE));
                if (d00 < minv0) { minv0 = d00; mini0 = code0; }
                if (d01 < minv0) { minv0 = d01; mini0 = code0 + 1; }
                if (d10 < minv1) { minv1 = d10; mini1 = code0; }
                if (d11 < minv1) { minv1 = d11; mini1 = code0 + 1; }
            }
        }
        __syncthreads();
    }

    #pragma unroll
    for (int off = 1; off <= 2; off <<= 1) {
        float ov = __shfl_xor_sync(0xffffffffu, minv0, off);
        int oi = __shfl_xor_sync(0xffffffffu, mini0, off);
        if (ov < minv0 || (ov == minv0 && oi < mini0)) { minv0 = ov; mini0 = oi; }
        ov = __shfl_xor_sync(0xffffffffu, minv1, off);
        oi = __shfl_xor_sync(0xffffffffu, mini1, off);
        if (ov < minv1 || (ov == minv1 && oi < mini1)) { minv1 = ov; mini1 = oi; }
    }
    if (tg == 0) {
        SMINI[w * 16 + g] = mini0;
        SMINI[w * 16 + g + 8] = mini1;
    }
    __syncthreads();

    float* red = LATN;
    if (tid < 128) {
        int ind = SMINI[tid];
        onehot[(size_t)(r0 + tid) * KCB + ind] = 1.0f;
        const float* ev = emb + (size_t)ind * 64;
        const float* lp = lat + (size_t)(r0 + tid) * 64;
        float s = 0.0f;
        for (int j = 0; j < 64; j++) {
            float qv = ev[j];
            float d = qv - lp[j];
            s = fmaf(d, d, s);
            qout[(size_t)(r0 + tid) * 64 + j] = qv;
        }
        red[tid] = s;
    }
    __syncthreads();
    for (int s2 = 64; s2 > 0; s2 >>= 1) {
        if (tid < s2) red[tid] += red[tid + s2];
        __syncthreads();
    }
    if (tid == 0) g_partial[blockIdx.x] = red[0];
}

__global__ void loss_kernel(float* __restrict__ out) {
    __shared__ float s[256];
    int tid = threadIdx.x;
    s[tid] = g_partial[tid];
    __syncthreads();
    for (int off = 128; off; off >>= 1) {
        if (tid < off) s[tid] += s[tid + off];
        __syncthreads();
    }
    if (tid == 0) {
        float m = s[0] * (1.0f / ((float)NB * (float)LATD));
        out[0] = __fadd_rn(__fmul_rn(1.25f, m), m);
    }
}

// ---------------- launch ----------------
extern "C" void kernel_launch(void* const* d_in, const int* in_sizes, int n_in,
                              void* d_out, int out_size) {
    const float* x    = (const float*)d_in[0];
    const float* eW1  = (const float*)d_in[1];
    const float* eb1  = (const float*)d_in[2];
    const float* eW2  = (const float*)d_in[3];
    const float* eb2  = (const float*)d_in[4];
    const float* eW3  = (const float*)d_in[5];
    const float* eb3  = (const float*)d_in[6];
    const float* emb  = (const float*)d_in[7];
    const float* dW1  = (const float*)d_in[8];
    const float* db1  = (const float*)d_in[9];
    const float* dW2  = (const float*)d_in[10];
    const float* db2  = (const float*)d_in[11];
    const float* dWmu = (const float*)d_in[12];
    const float* dbmu = (const float*)d_in[13];
    const float* dWlv = (const float*)d_in[14];
    const float* dblv = (const float*)d_in[15];

    float* out   = (float*)d_out;
    float* xhat  = out;
    float* xvar  = out + (size_t)NB * INDIM;
    float* oneh  = out + (size_t)2 * NB * INDIM;
    float* lossp = out + ((size_t)out_size - 1);

    float *lat, *q;
    uint4 *xF, *h1F, *h2F, *qF, *h3F, *h4F, *wF;
    cudaGetSymbolAddress((void**)&lat, g_lat);
    cudaGetSymbolAddress((void**)&q,   g_q);
    cudaGetSymbolAddress((void**)&xF,  g_xF);
    cudaGetSymbolAddress((void**)&h1F, g_h1F);
    cudaGetSymbolAddress((void**)&h2F, g_h2F);
    cudaGetSymbolAddress((void**)&qF,  g_qF);
    cudaGetSymbolAddress((void**)&h3F, g_h3F);
    cudaGetSymbolAddress((void**)&h4F, g_h4F);
    cudaGetSymbolAddress((void**)&wF,  g_wF);

    cudaFuncSetAttribute(vq_mma_kernel, cudaFuncAttributeMaxDynamicSharedMemorySize, VQ_SMEM);

    // fused prep + first zero-fill slice
    prep_kernel<<<4308, 256>>>(emb, x, eW1, eW2, eW3, dW1, dW2, dWmu, dWlv, oneh);

    // encoder (bf16 3-split, 6 products) + zero-fill slices
    hmlp_kernel< 8, 256, 128, true,  true, 0><<<dim3(256, 2, 1), 256>>>(xF,  wF + OFF_W1, eb1, 1.0f, nullptr, h1F, nullptr, nullptr, nullptr, oneh, Z_PREP, Z_L1);
    hmlp_kernel<16, 128, 128, true,  true, 0><<<dim3(256, 1, 1), 256>>>(h1F, wF + OFF_W2, eb2, 1.0f, nullptr, h2F, nullptr, nullptr, nullptr, oneh, Z_PREP + Z_L1, Z_L2);
    hmlp_kernel< 8,  64,  64, false, true, 2><<<dim3(256, 1, 1), 256>>>(h2F, wF + OFF_W3, eb3, 1.0f, lat, nullptr, nullptr, nullptr, nullptr, oneh, Z_PREP + Z_L1 + Z_L2, Z_L3);

    // vector quantize (scatter-only one-hot now)
    vq_mma_kernel<<<NB / 128, 256, VQ_SMEM>>>(lat, emb, oneh, q);

    // decoder (fp16 2-split, 3 products); mu+lv fused via grid.z
    convA_fp2<<<RT_TOT * 4 * 32 / 256, 256>>>(q, qF, 4);
    hmlp_kernel< 4, 128, 128, true,  false, 1><<<dim3(256, 1, 1), 256>>>(qF,  wF + OFF_W4, db1,  MLP_DS, nullptr, h3F, nullptr, nullptr, nullptr, nullptr, 0, 0);
    hmlp_kernel< 8, 256, 128, true,  false, 1><<<dim3(256, 2, 1), 256>>>(h3F, wF + OFF_W5, db2,  MLP_DS, nullptr, h4F, nullptr, nullptr, nullptr, nullptr, 0, 0);
    hmlp_kernel<16, 128, 128, false, false, 2><<<dim3(256, 1, 2), 256>>>(h4F, wF + OFF_W6, dbmu, MLP_DS, xhat, nullptr, wF + OFF_W7, dblv, xvar, nullptr, 0, 0);

    // scalar vq_loss
    loss_kernel<<<1, 256>>>(lossp);
}

// round 11
// speedup vs baseline: 1.2959x; 1.2959x over previous
#include <cuda_runtime.h>
#include <cuda_bf16.h>
#include <cuda_fp16.h>
#include <cstdint>
#include <cstddef>

// ---------------- problem constants ----------------
#define NB    32768
#define INDIM 128
#define LATD  64
#define KCB   8192
#define NTILE 64
#define NTILES (KCB / NTILE)        // 128
#define TILE_U32 4096               // VQ per-tile fragment plane
#define TILE_BYTES 16384

// VQ scales (proven): A x 2^8, B x 2^17 -> 2*dot = C * 2^-24
#define ASCALE 256.0f
#define BSCALE 131072.0f
#define DESCALE 5.9604644775390625e-8f  // 2^-24

// decoder MLP scales: act x 2^4, W x 2^12 -> dot = C * 2^-16
#define MLP_AS 16.0f
#define MLP_WS 4096.0f
#define MLP_DS 1.52587890625e-5f        // 2^-16

#define RT_TOT (NB / 16)                 // 2048 row-tiles

// ---------------- scratch (device globals; no allocations) ----------------
__device__ float g_lat[(size_t)NB * LATD];
__device__ float g_embn[KCB];
__device__ uint32_t g_embF[(size_t)NTILES * TILE_U32];
__device__ float g_partial[256];

// activation fragment planes
__device__ uint4 g_xF [(size_t)RT_TOT * 8 * 3 * 32];
__device__ uint4 g_h1F[(size_t)RT_TOT * 16 * 3 * 32];
__device__ uint4 g_h2F[(size_t)RT_TOT * 8 * 3 * 32];
__device__ uint4 g_qF [(size_t)RT_TOT * 4 * 2 * 32];
__device__ uint4 g_h3F[(size_t)RT_TOT * 8 * 2 * 32];
__device__ uint4 g_h4F[(size_t)RT_TOT * 16 * 2 * 32];

// weight fragment planes, layer offsets (uint4 units)
#define OFF_W1 0
#define OFF_W2 12288
#define OFF_W3 24576
#define OFF_W4 27648
#define OFF_W5 29696
#define OFF_W6 37888
#define OFF_W7 46080
__device__ uint4 g_wF[54272];

// ---------------- helpers ----------------
__device__ __forceinline__ uint32_t smem_u32(const void* p) {
    uint32_t a;
    asm("{ .reg .u64 t; cvta.to.shared.u64 t, %1; cvt.u32.u64 %0, t; }" : "=r"(a) : "l"(p));
    return a;
}
__device__ __forceinline__ void cp16(uint32_t dst, const void* src) {
    asm volatile("cp.async.cg.shared.global [%0], [%1], 16;" :: "r"(dst), "l"(src));
}
__device__ __forceinline__ void split2h(float v, unsigned short& s0, unsigned short& s1) {
    __half h0 = __float2half_rn(v);
    float r = v - __half2float(h0);
    __half h1 = __float2half_rn(r);
    s0 = __half_as_ushort(h0);
    s1 = __half_as_ushort(h1);
}
__device__ __forceinline__ void split3b(float v, unsigned short& s0, unsigned short& s1, unsigned short& s2) {
    __nv_bfloat16 b0 = __float2bfloat16_rn(v);
    float r1 = v - __bfloat162float(b0);
    __nv_bfloat16 b1 = __float2bfloat16_rn(r1);
    float r2 = r1 - __bfloat162float(b1);
    __nv_bfloat16 b2 = __float2bfloat16_rn(r2);
    s0 = __bfloat16_as_ushort(b0);
    s1 = __bfloat16_as_ushort(b1);
    s2 = __bfloat16_as_ushort(b2);
}
__device__ __forceinline__ void mma_f16(float* C, const uint32_t* A, uint32_t b0, uint32_t b1) {
    asm volatile("mma.sync.aligned.m16n8k16.row.col.f32.f16.f16.f32 "
        "{%0,%1,%2,%3}, {%4,%5,%6,%7}, {%8,%9}, {%0,%1,%2,%3};"
        : "+f"(C[0]), "+f"(C[1]), "+f"(C[2]), "+f"(C[3])
        : "r"(A[0]), "r"(A[1]), "r"(A[2]), "r"(A[3]), "r"(b0), "r"(b1));
}
__device__ __forceinline__ void mma_bf16(float* C, const uint32_t* A, uint32_t b0, uint32_t b1) {
    asm volatile("mma.sync.aligned.m16n8k16.row.col.f32.bf16.bf16.f32 "
        "{%0,%1,%2,%3}, {%4,%5,%6,%7}, {%8,%9}, {%0,%1,%2,%3};"
        : "+f"(C[0]), "+f"(C[1]), "+f"(C[2]), "+f"(C[3])
        : "r"(A[0]), "r"(A[1]), "r"(A[2]), "r"(A[3]), "r"(b0), "r"(b1));
}
__device__ __forceinline__ uint32_t pack2(unsigned short a, unsigned short b) {
    return (uint32_t)a | ((uint32_t)b << 16);
}

// ---------------- prep bodies (device functions, fused into one launch) ----------------
__device__ __forceinline__ void embn_body(const float* __restrict__ emb, int t) {
    int code = t >> 5;
    int lane = t & 31;
    if (code >= KCB) return;
    float v0 = emb[code * 64 + lane];
    float v1 = emb[code * 64 + 32 + lane];
    float s = fmaf(v0, v0, v1 * v1);
    #pragma unroll
    for (int off = 16; off; off >>= 1)
        s += __shfl_down_sync(0xffffffffu, s, off);
    if (lane == 0) g_embn[code] = s;
}

__device__ __forceinline__ void embfrag_body(const float* __restrict__ emb, int idx) {
    if (idx >= NTILES * 4 * 2 * 8 * 32) return;
    int l = idx & 31;
    int r = idx >> 5;
    int n = r & 7;
    int r2 = r >> 3;
    int s = r2 & 1;
    int r3 = r2 >> 1;
    int kt = r3 & 3;
    int t = r3 >> 2;
    int g = l >> 2, tg = l & 3;
    int code = t * 64 + n * 8 + g;
    const float* e = emb + (size_t)code * 64 + kt * 16;
    float vv[4] = {e[2 * tg] * BSCALE, e[2 * tg + 1] * BSCALE,
                   e[2 * tg + 8] * BSCALE, e[2 * tg + 9] * BSCALE};
    unsigned short p[4];
    #pragma unroll
    for (int i = 0; i < 4; i++) {
        unsigned short c0, c1;
        split2h(vv[i], c0, c1);
        p[i] = (s == 0) ? c0 : c1;
    }
    uint2 out;
    out.x = pack2(p[0], p[1]);
    out.y = pack2(p[2], p[3]);
    ((uint2*)g_embF)[idx] = out;
}

__device__ __forceinline__ void wfrag_bf3_body(const float* __restrict__ W, uint4* __restrict__ out,
                                               int KT, int NOUTL, int idx) {
    if (idx >= KT * 3 * (NOUTL / 16) * 32) return;
    int l = idx & 31;
    int t2 = idx >> 5;
    int np = t2 % (NOUTL / 16);
    int t3 = t2 / (NOUTL / 16);
    int s = t3 % 3;
    int kt = t3 / 3;
    int g = l >> 2, tg = l & 3;
    int Kw = KT * 16;
    uint32_t r[4];
    #pragma unroll
    for (int j = 0; j < 2; j++) {
        int n = 2 * np + j;
        const float* e = W + (size_t)(n * 8 + g) * Kw + kt * 16;
        float vv[4] = {e[2 * tg], e[2 * tg + 1], e[2 * tg + 8], e[2 * tg + 9]};
        unsigned short sel[4];
        #pragma unroll
        for (int i = 0; i < 4; i++) {
            unsigned short a, b, c;
            split3b(vv[i], a, b, c);
            sel[i] = (s == 0) ? a : (s == 1) ? b : c;
        }
        r[2 * j + 0] = pack2(sel[0], sel[1]);
        r[2 * j + 1] = pack2(sel[2], sel[3]);
    }
    out[idx] = make_uint4(r[0], r[1], r[2], r[3]);
}

__device__ __forceinline__ void wfrag_fp2_body(const float* __restrict__ W, uint4* __restrict__ out,
                                               int KT, int NOUTL, int idx) {
    if (idx >= KT * 2 * (NOUTL / 16) * 32) return;
    int l = idx & 31;
    int t2 = idx >> 5;
    int np = t2 % (NOUTL / 16);
    int t3 = t2 / (NOUTL / 16);
    int s = t3 & 1;
    int kt = t3 >> 1;
    int g = l >> 2, tg = l & 3;
    int Kw = KT * 16;
    uint32_t r[4];
    #pragma unroll
    for (int j = 0; j < 2; j++) {
        int n = 2 * np + j;
        const float* e = W + (size_t)(n * 8 + g) * Kw + kt * 16;
        float vv[4] = {e[2 * tg] * MLP_WS, e[2 * tg + 1] * MLP_WS,
                       e[2 * tg + 8] * MLP_WS, e[2 * tg + 9] * MLP_WS};
        unsigned short sel[4];
        #pragma unroll
        for (int i = 0; i < 4; i++) {
            unsigned short a, b;
            split2h(vv[i], a, b);
            sel[i] = (s == 0) ? a : b;
        }
        r[2 * j + 0] = pack2(sel[0], sel[1]);
        r[2 * j + 1] = pack2(sel[2], sel[3]);
    }
    out[idx] = make_uint4(r[0], r[1], r[2], r[3]);
}

__device__ __forceinline__ void convA_bf3_body(const float* __restrict__ in, uint4* __restrict__ out,
                                               int KT, int idx) {
    if (idx >= RT_TOT * KT * 32) return;
    int l = idx & 31;
    int t2 = idx >> 5;
    int kt = t2 % KT;
    int rt = t2 / KT;
    int g = l >> 2, tg = l & 3;
    int Kw = KT * 16;
    const float* p = in + (size_t)(rt * 16 + g) * Kw + kt * 16 + 2 * tg;
    float2 v0 = *(const float2*)p;
    float2 v1 = *(const float2*)(p + 8);
    float2 v2 = *(const float2*)(p + 8 * Kw);
    float2 v3 = *(const float2*)(p + 8 * Kw + 8);
    float vv[8] = {v0.x, v0.y, v2.x, v2.y, v1.x, v1.y, v3.x, v3.y};
    unsigned short us[8][3];
    #pragma unroll
    for (int i = 0; i < 8; i++) split3b(vv[i], us[i][0], us[i][1], us[i][2]);
    size_t base = (size_t)t2 * 3 * 32 + l;
    #pragma unroll
    for (int s = 0; s < 3; s++)
        out[base + (size_t)s * 32] = make_uint4(pack2(us[0][s], us[1][s]), pack2(us[2][s], us[3][s]),
                                                pack2(us[4][s], us[5][s]), pack2(us[6][s], us[7][s]));
}

// fused prep: block ranges dispatch independent elementwise work
__global__ __launch_bounds__(256) void prep_kernel(
    const float* __restrict__ emb, const float* __restrict__ x,
    const float* __restrict__ eW1, const float* __restrict__ eW2, const float* __restrict__ eW3,
    const float* __restrict__ dW1, const float* __restrict__ dW2,
    const float* __restrict__ dWmu, const float* __restrict__ dWlv)
{
    int bid = blockIdx.x;
    int tid = threadIdx.x;
    if (bid < 1024) {
        embn_body(emb, bid * 256 + tid);
    } else if (bid < 2048) {
        embfrag_body(emb, (bid - 1024) * 256 + tid);
    } else if (bid < 2096) {
        wfrag_bf3_body(eW1, g_wF + OFF_W1, 8, 256, (bid - 2048) * 256 + tid);
    } else if (bid < 2144) {
        wfrag_bf3_body(eW2, g_wF + OFF_W2, 16, 128, (bid - 2096) * 256 + tid);
    } else if (bid < 2156) {
        wfrag_bf3_body(eW3, g_wF + OFF_W3, 8, 64, (bid - 2144) * 256 + tid);
    } else if (bid < 2164) {
        wfrag_fp2_body(dW1, g_wF + OFF_W4, 4, 128, (bid - 2156) * 256 + tid);
    } else if (bid < 2196) {
        wfrag_fp2_body(dW2, g_wF + OFF_W5, 8, 256, (bid - 2164) * 256 + tid);
    } else if (bid < 2228) {
        wfrag_fp2_body(dWmu, g_wF + OFF_W6, 16, 128, (bid - 2196) * 256 + tid);
    } else if (bid < 2260) {
        wfrag_fp2_body(dWlv, g_wF + OFF_W7, 16, 128, (bid - 2228) * 256 + tid);
    } else {
        convA_bf3_body(x, g_xF, 8, (bid - 2260) * 256 + tid);
    }
}

// ---------------- tensor MLP layer (round-9 proven) ----------------
// OUTMODE: 0 = bf3 frag planes, 1 = fp2 frag planes (x MLP_AS), 2 = fp32 row-major
template <int KT, int NOUT, int CTILE, bool RELU, bool INBF, int OUTMODE>
__global__ __launch_bounds__(256, 2) void hmlp_kernel(
    const uint4* __restrict__ Af, const uint4* __restrict__ Wf,
    const float* __restrict__ bias, float dscale,
    float* __restrict__ outF, uint4* __restrict__ outFrag,
    const uint4* __restrict__ Wf2, const float* __restrict__ bias2,
    float* __restrict__ outF2)
{
    constexpr int INS = INBF ? 3 : 2;
    constexpr int NCOL = CTILE / 8;
    constexpr int NPT = CTILE / 16;      // column pairs in this CTA tile
    constexpr int NPW = NOUT / 16;       // total column pairs
    constexpr int GP = INBF ? 2 : 4;     // npp group size for interleave
    constexpr int NG = NPT / GP;
    const int l = threadIdx.x & 31;
    const int wid = threadIdx.x >> 5;
    const int rt = blockIdx.x * 8 + wid;
    const int c0 = blockIdx.y * CTILE;
    const int np0 = c0 >> 4;

    if (blockIdx.z) { Wf = Wf2; bias = bias2; outF = outF2; }

    float C[NCOL][4];
    #pragma unroll
    for (int n = 0; n < NCOL; n++)
        C[n][0] = C[n][1] = C[n][2] = C[n][3] = 0.0f;

    for (int kt = 0; kt < KT; kt++) {
        const uint4* ab = Af + (size_t)(rt * KT + kt) * INS * 32 + l;
        uint4 a0 = ab[0];
        uint4 a1 = ab[32];
        uint4 a2;
        if constexpr (INBF) a2 = ab[64];
        const uint4* wb = Wf + ((size_t)kt * INS * NPW + np0) * 32 + l;
        #pragma unroll
        for (int grp = 0; grp < NG; grp++) {
            uint4 u[GP][INS];
            #pragma unroll
            for (int j = 0; j < GP; j++)
                #pragma unroll
                for (int s = 0; s < INS; s++)
                    u[j][s] = wb[(s * NPW + grp * GP + j) * 32];
            #pragma unroll
            for (int j = 0; j < GP; j++) {
                int n0 = 2 * (grp * GP + j);
                if constexpr (INBF) {
                    mma_bf16(C[n0],     (const uint32_t*)&a0, u[j][0].x, u[j][0].y);
                    mma_bf16(C[n0 + 1], (const uint32_t*)&a0, u[j][0].z, u[j][0].w);
                } else {
                    mma_f16(C[n0],     (const uint32_t*)&a0, u[j][0].x, u[j][0].y);
                    mma_f16(C[n0 + 1], (const uint32_t*)&a0, u[j][0].z, u[j][0].w);
                }
            }
            #pragma unroll
            for (int j = 0; j < GP; j++) {
                int n0 = 2 * (grp * GP + j);
                if constexpr (INBF) {
                    mma_bf16(C[n0],     (const uint32_t*)&a0, u[j][1].x, u[j][1].y);
                    mma_bf16(C[n0 + 1], (const uint32_t*)&a0, u[j][1].z, u[j][1].w);
                } else {
                    mma_f16(C[n0],     (const uint32_t*)&a0, u[j][1].x, u[j][1].y);
                    mma_f16(C[n0 + 1], (const uint32_t*)&a0, u[j][1].z, u[j][1].w);
                }
            }
            #pragma unroll
            for (int j = 0; j < GP; j++) {
                int n0 = 2 * (grp * GP + j);
                if constexpr (INBF) {
                    mma_bf16(C[n0],     (const uint32_t*)&a1, u[j][0].x, u[j][0].y);
                    mma_bf16(C[n0 + 1], (const uint32_t*)&a1, u[j][0].z, u[j][0].w);
                } else {
                    mma_f16(C[n0],     (const uint32_t*)&a1, u[j][0].x, u[j][0].y);
                    mma_f16(C[n0 + 1], (const uint32_t*)&a1, u[j][0].z, u[j][0].w);
                }
            }
            if constexpr (INBF) {
                #pragma unroll
                for (int j = 0; j < GP; j++) {
                    int n0 = 2 * (grp * GP + j);
                    mma_bf16(C[n0],     (const uint32_t*)&a1, u[j][1].x, u[j][1].y);
                    mma_bf16(C[n0 + 1], (const uint32_t*)&a1, u[j][1].z, u[j][1].w);
                }
                #pragma unroll
                for (int j = 0; j < GP; j++) {
                    int n0 = 2 * (grp * GP + j);
                    mma_bf16(C[n0],     (const uint32_t*)&a0, u[j][2].x, u[j][2].y);
                    mma_bf16(C[n0 + 1], (const uint32_t*)&a0, u[j][2].z, u[j][2].w);
                }
                #pragma unroll
                for (int j = 0; j < GP; j++) {
                    int n0 = 2 * (grp * GP + j);
                    mma_bf16(C[n0],     (const uint32_t*)&a2, u[j][0].x, u[j][0].y);
                    mma_bf16(C[n0 + 1], (const uint32_t*)&a2, u[j][0].z, u[j][0].w);
                }
            }
        }
    }

    const int g = l >> 2, tg = l & 3;
    #pragma unroll
    for (int n = 0; n < NCOL; n++) {
        float2 b = *(const float2*)&bias[c0 + n * 8 + 2 * tg];
        C[n][0] = __fadd_rn(__fmul_rn(C[n][0], dscale), b.x);
        C[n][1] = __fadd_rn(__fmul_rn(C[n][1], dscale), b.y);
        C[n][2] = __fadd_rn(__fmul_rn(C[n][2], dscale), b.x);
        C[n][3] = __fadd_rn(__fmul_rn(C[n][3], dscale), b.y);
        if (RELU) {
            C[n][0] = fmaxf(C[n][0], 0.0f);
            C[n][1] = fmaxf(C[n][1], 0.0f);
            C[n][2] = fmaxf(C[n][2], 0.0f);
            C[n][3] = fmaxf(C[n][3], 0.0f);
        }
    }

    if constexpr (OUTMODE == 2) {
        const int row0 = rt * 16 + g;
        #pragma unroll
        for (int n = 0; n < NCOL; n++) {
            float* po = outF + (size_t)row0 * NOUT + c0 + n * 8 + 2 * tg;
            *(float2*)po = make_float2(C[n][0], C[n][1]);
            *(float2*)(po + (size_t)8 * NOUT) = make_float2(C[n][2], C[n][3]);
        }
    } else if constexpr (OUTMODE == 0) {
        #pragma unroll
        for (int ktl = 0; ktl < NCOL / 2; ktl++) {
            float vv[8] = {C[2 * ktl][0], C[2 * ktl][1], C[2 * ktl][2], C[2 * ktl][3],
                           C[2 * ktl + 1][0], C[2 * ktl + 1][1], C[2 * ktl + 1][2], C[2 * ktl + 1][3]};
            unsigned short us[8][3];
            #pragma unroll
            for (int i = 0; i < 8; i++) split3b(vv[i], us[i][0], us[i][1], us[i][2]);
            size_t base = (size_t)(rt * (NOUT / 16) + np0 + ktl) * 3 * 32 + l;
            #pragma unroll
            for (int s = 0; s < 3; s++)
                outFrag[base + (size_t)s * 32] =
                    make_uint4(pack2(us[0][s], us[1][s]), pack2(us[2][s], us[3][s]),
                               pack2(us[4][s], us[5][s]), pack2(us[6][s], us[7][s]));
        }
    } else {
        #pragma unroll
        for (int ktl = 0; ktl < NCOL / 2; ktl++) {
            float vv[8] = {C[2 * ktl][0], C[2 * ktl][1], C[2 * ktl][2], C[2 * ktl][3],
                           C[2 * ktl + 1][0], C[2 * ktl + 1][1], C[2 * ktl + 1][2], C[2 * ktl + 1][3]};
            unsigned short us[8][2];
            #pragma unroll
            for (int i = 0; i < 8; i++) split2h(vv[i] * MLP_AS, us[i][0], us[i][1]);
            size_t base = (size_t)(rt * (NOUT / 16) + np0 + ktl) * 2 * 32 + l;
            #pragma unroll
            for (int s = 0; s < 2; s++)
                outFrag[base + (size_t)s * 32] =
                    make_uint4(pack2(us[0][s], us[1][s]), pack2(us[2][s], us[3][s]),
                               pack2(us[4][s], us[5][s]), pack2(us[6][s], us[7][s]));
        }
    }
}

// ---------------- VQ kernel (round-9 + fused qF fragment emission) ----------------
#define SM_EMBN 32768
#define SM_LATN 65536
#define SM_MINI 66048
#define VQ_SMEM 66560

__global__ __launch_bounds__(256, 2) void vq_mma_kernel(const float* __restrict__ lat,
                                                        const float* __restrict__ emb,
                                                        float* __restrict__ onehot,
                                                        uint4* __restrict__ qF) {
    extern __shared__ __align__(16) unsigned char smem[];
    float* EMBN = (float*)(smem + SM_EMBN);
    float* LATN = (float*)(smem + SM_LATN);
    int*   SMINI = (int*)(smem + SM_MINI);
    const int tid = threadIdx.x;
    const int w = tid >> 5, l = tid & 31, g = l >> 2, tg = l & 3;
    const int r0 = blockIdx.x * 128;
    const uint32_t sb = smem_u32(smem);

    {
        const char* src = (const char*)g_embF;
        #pragma unroll
        for (int i = 0; i < 4; i++)
            cp16(sb + (uint32_t)(i * 256 + tid) * 16u, src + (size_t)(i * 256 + tid) * 16);
        asm volatile("cp.async.commit_group;" ::: "memory");
    }
    {
        float4* d = (float4*)EMBN;
        const float4* s = (const float4*)(lat + (size_t)r0 * 64);
        #pragma unroll
        for (int i = 0; i < 8; i++) d[i * 256 + tid] = s[i * 256 + tid];
    }
    __syncthreads();

    if (tid < 128) {
        const float* row = EMBN + tid * 64;
        float s = 0.0f;
        for (int j = 0; j < 64; j++) s = fmaf(row[j], row[j], s);
        LATN[tid] = s;
    }

    uint32_t A0[4][4], A1[4][4];
    {
        const float2* L2 = (const float2*)EMBN;
        int row0 = w * 16 + g;
        #pragma unroll
        for (int kt = 0; kt < 4; kt++) {
            #pragma unroll
            for (int half = 0; half < 2; half++) {
                int rr = row0 + half * 8;
                #pragma unroll
                for (int chunk = 0; chunk < 2; chunk++) {
                    float2 v = L2[rr * 32 + kt * 8 + tg + chunk * 4];
                    unsigned short x0, x1, y0, y1;
                    split2h(v.x * ASCALE, x0, x1);
                    split2h(v.y * ASCALE, y0, y1);
                    int ai = half + 2 * chunk;
                    A0[kt][ai] = pack2(x0, y0);
                    A1[kt][ai] = pack2(x1, y1);
                }
            }
        }
    }
    __syncthreads();
    {
        float4* d = (float4*)EMBN;
        const float4* s = (const float4*)g_embn;
        #pragma unroll
        for (int i = 0; i < 8; i++) d[i * 256 + tid] = s[i * 256 + tid];
    }
    __syncthreads();
    const float ln0 = LATN[w * 16 + g];
    const float ln1 = LATN[w * 16 + g + 8];

    float minv0 = 3.402823466e38f, minv1 = 3.402823466e38f;
    int mini0 = 0, mini1 = 0;

    for (int t = 0; t < NTILES; t++) {
        const int cur = t & 1;
        if (t + 1 < NTILES) {
            const uint32_t dst = sb + (uint32_t)(cur ^ 1) * TILE_BYTES;
            const char* src = (const char*)g_embF + (size_t)(t + 1) * TILE_BYTES;
            #pragma unroll
            for (int i = 0; i < 4; i++)
                cp16(dst + (uint32_t)(i * 256 + tid) * 16u, src + (size_t)(i * 256 + tid) * 16);
            asm volatile("cp.async.commit_group;" ::: "memory");
            asm volatile("cp.async.wait_group 1;" ::: "memory");
        } else {
            asm volatile("cp.async.wait_group 0;" ::: "memory");
        }
        __syncthreads();

        const uint2* BT = (const uint2*)(smem + (size_t)cur * TILE_BYTES);
        #pragma unroll
        for (int batch = 0; batch < 2; batch++) {
            float C[4][4];
            #pragma unroll
            for (int c = 0; c < 4; c++)
                C[c][0] = C[c][1] = C[c][2] = C[c][3] = 0.0f;
            #pragma unroll
            for (int kt = 0; kt < 4; kt++) {
                #pragma unroll
                for (int c = 0; c < 4; c++) {
                    const int n = batch * 4 + c;
                    uint2 b0 = BT[((kt * 2 + 0) * 8 + n) * 32 + l];
                    uint2 b1 = BT[((kt * 2 + 1) * 8 + n) * 32 + l];
                    mma_f16(C[c], A0[kt], b0.x, b0.y);
                    mma_f16(C[c], A0[kt], b1.x, b1.y);
                    mma_f16(C[c], A1[kt], b0.x, b0.y);
                }
            }
            #pragma unroll
            for (int c = 0; c < 4; c++) {
                const int code0 = t * 64 + (batch * 4 + c) * 8 + 2 * tg;
                float2 en = *(const float2*)(EMBN + code0);
                float d00 = __fsub_rn(__fadd_rn(ln0, en.x), __fmul_rn(C[c][0], DESCALE));
                float d01 = __fsub_rn(__fadd_rn(ln0, en.y), __fmul_rn(C[c][1], DESCALE));
                float d10 = __fsub_rn(__fadd_rn(ln1, en.x), __fmul_rn(C[c][2], DESCALE));
                float d11 = __fsub_rn(__fadd_rn(ln1, en.y), __fmul_rn(C[c][3], DESCALE));
                if (d00 < minv0) { minv0 = d00; mini0 = code0; }
                if (d01 < minv0) { minv0 = d01; mini0 = code0 + 1; }
                if (d10 < minv1) { minv1 = d10; mini1 = code0; }
                if (d11 < minv1) { minv1 = d11; mini1 = code0 + 1; }
            }
        }
        // interleaved one-hot zero fill for this tile's code slice (proven overlapped)
        {
            const float4 z = make_float4(0.f, 0.f, 0.f, 0.f);
            float* base = onehot + (size_t)r0 * KCB + t * 64 + (tid & 15) * 4;
            for (int rr = (tid >> 4); rr < 128; rr += 16)
                *(float4*)(base + (size_t)rr * KCB) = z;
        }
        __syncthreads();
    }

    #pragma unroll
    for (int off = 1; off <= 2; off <<= 1) {
        float ov = __shfl_xor_sync(0xffffffffu, minv0, off);
        int oi = __shfl_xor_sync(0xffffffffu, mini0, off);
        if (ov < minv0 || (ov == minv0 && oi < mini0)) { minv0 = ov; mini0 = oi; }
        ov = __shfl_xor_sync(0xffffffffu, minv1, off);
        oi = __shfl_xor_sync(0xffffffffu, mini1, off);
        if (ov < minv1 || (ov == minv1 && oi < mini1)) { minv1 = ov; mini1 = oi; }
    }
    if (tg == 0) {
        SMINI[w * 16 + g] = mini0;
        SMINI[w * 16 + g + 8] = mini1;
    }
    __syncthreads();

    // finale: one-hot scatter, q gather into smem, commitment partial
    float* QS = EMBN;   // 128 rows x 64 floats = 32 KB (EMBN region free now)
    float* red = LATN;
    if (tid < 128) {
        int ind = SMINI[tid];
        onehot[(size_t)(r0 + tid) * KCB + ind] = 1.0f;
        const float* ev = emb + (size_t)ind * 64;
        const float* lp = lat + (size_t)(r0 + tid) * 64;
        float s = 0.0f;
        for (int j = 0; j < 64; j++) {
            float qv = ev[j];
            float d = qv - lp[j];
            s = fmaf(d, d, s);
            QS[tid * 64 + j] = qv;
        }
        red[tid] = s;
    }
    __syncthreads();

    // fused qF fragment emission (bit-identical to convA_fp2 on q)
    {
        const int rt = blockIdx.x * 8 + w;   // global row-tile; warp w owns rows w*16..w*16+15
        const float2* Q2 = (const float2*)QS;
        #pragma unroll
        for (int kt = 0; kt < 4; kt++) {
            float2 v0 = Q2[(w * 16 + g) * 32 + kt * 8 + tg];
            float2 v1 = Q2[(w * 16 + g) * 32 + kt * 8 + tg + 4];
            float2 v2 = Q2[(w * 16 + g + 8) * 32 + kt * 8 + tg];
            float2 v3 = Q2[(w * 16 + g + 8) * 32 + kt * 8 + tg + 4];
            float vv[8] = {v0.x, v0.y, v2.x, v2.y, v1.x, v1.y, v3.x, v3.y};
            unsigned short us[8][2];
            #pragma unroll
            for (int i = 0; i < 8; i++) split2h(vv[i] * MLP_AS, us[i][0], us[i][1]);
            size_t base = (size_t)(rt * 4 + kt) * 2 * 32 + l;
            #pragma unroll
            for (int s = 0; s < 2; s++)
                qF[base + (size_t)s * 32] =
                    make_uint4(pack2(us[0][s], us[1][s]), pack2(us[2][s], us[3][s]),
                               pack2(us[4][s], us[5][s]), pack2(us[6][s], us[7][s]));
        }
    }
    __syncthreads();
    for (int s2 = 64; s2 > 0; s2 >>= 1) {
        if (tid < s2) red[tid] += red[tid + s2];
        __syncthreads();
    }
    if (tid == 0) g_partial[blockIdx.x] = red[0];
}

__global__ void loss_kernel(float* __restrict__ out) {
    __shared__ float s[256];
    int tid = threadIdx.x;
    s[tid] = g_partial[tid];
    __syncthreads();
    for (int off = 128; off; off >>= 1) {
        if (tid < off) s[tid] += s[tid + off];
        __syncthreads();
    }
    if (tid == 0) {
        float m = s[0] * (1.0f / ((float)NB * (float)LATD));
        out[0] = __fadd_rn(__fmul_rn(1.25f, m), m);
    }
}

// ---------------- launch ----------------
extern "C" void kernel_launch(void* const* d_in, const int* in_sizes, int n_in,
                              void* d_out, int out_size) {
    const float* x    = (const float*)d_in[0];
    const float* eW1  = (const float*)d_in[1];
    const float* eb1  = (const float*)d_in[2];
    const float* eW2  = (const float*)d_in[3];
    const float* eb2  = (const float*)d_in[4];
    const float* eW3  = (const float*)d_in[5];
    const float* eb3  = (const float*)d_in[6];
    const float* emb  = (const float*)d_in[7];
    const float* dW1  = (const float*)d_in[8];
    const float* db1  = (const float*)d_in[9];
    const float* dW2  = (const float*)d_in[10];
    const float* db2  = (const float*)d_in[11];
    const float* dWmu = (const float*)d_in[12];
    const float* dbmu = (const float*)d_in[13];
    const float* dWlv = (const float*)d_in[14];
    const float* dblv = (const float*)d_in[15];

    float* out   = (float*)d_out;
    float* xhat  = out;
    float* xvar  = out + (size_t)NB * INDIM;
    float* oneh  = out + (size_t)2 * NB * INDIM;
    float* lossp = out + ((size_t)out_size - 1);

    float *lat;
    uint4 *xF, *h1F, *h2F, *qF, *h3F, *h4F, *wF;
    cudaGetSymbolAddress((void**)&lat, g_lat);
    cudaGetSymbolAddress((void**)&xF,  g_xF);
    cudaGetSymbolAddress((void**)&h1F, g_h1F);
    cudaGetSymbolAddress((void**)&h2F, g_h2F);
    cudaGetSymbolAddress((void**)&qF,  g_qF);
    cudaGetSymbolAddress((void**)&h3F, g_h3F);
    cudaGetSymbolAddress((void**)&h4F, g_h4F);
    cudaGetSymbolAddress((void**)&wF,  g_wF);

    cudaFuncSetAttribute(vq_mma_kernel, cudaFuncAttributeMaxDynamicSharedMemorySize, VQ_SMEM);

    // fused prep (embn + embfrag + all wfrags + x conversion) in ONE launch
    prep_kernel<<<4308, 256>>>(emb, x, eW1, eW2, eW3, dW1, dW2, dWmu, dWlv);

    // encoder (bf16 3-split, 6 products)
    hmlp_kernel< 8, 256, 128, true,  true, 0><<<dim3(256, 2, 1), 256>>>(xF,  wF + OFF_W1, eb1, 1.0f, nullptr, h1F, nullptr, nullptr, nullptr);
    hmlp_kernel<16, 128, 128, true,  true, 0><<<dim3(256, 1, 1), 256>>>(h1F, wF + OFF_W2, eb2, 1.0f, nullptr, h2F, nullptr, nullptr, nullptr);
    hmlp_kernel< 8,  64,  64, false, true, 2><<<dim3(256, 1, 1), 256>>>(h2F, wF + OFF_W3, eb3, 1.0f, lat, nullptr, nullptr, nullptr, nullptr);

    // vector quantize (+ one_hot + fused qF emission + partial loss)
    vq_mma_kernel<<<NB / 128, 256, VQ_SMEM>>>(lat, emb, oneh, qF);

    // decoder (fp16 2-split, 3 products); mu+lv fused via grid.z
    hmlp_kernel< 4, 128, 128, true,  false, 1><<<dim3(256, 1, 1), 256>>>(qF,  wF + OFF_W4, db1,  MLP_DS, nullptr, h3F, nullptr, nullptr, nullptr);
    hmlp_kernel< 8, 256, 128, true,  false, 1><<<dim3(256, 2, 1), 256>>>(h3F, wF + OFF_W5, db2,  MLP_DS, nullptr, h4F, nullptr, nullptr, nullptr);
    hmlp_kernel<16, 128, 128, false, false, 2><<<dim3(256, 1, 2), 256>>>(h4F, wF + OFF_W6, dbmu, MLP_DS, xhat, nullptr, wF + OFF_W7, dblv, xvar);

    // scalar vq_loss
    loss_kernel<<<1, 256>>>(lossp);
}